// round 1
// baseline (speedup 1.0000x reference)
#include <cuda_runtime.h>

// Problem constants
#define Nn 100000
#define Ee 200000
#define Gg 2500
#define FN 16
#define FE 8
#define H1c 32
#define H2c 16
#define WPB 8   // warps per block in edge kernels

// ---------------- scratch (device globals; no allocation allowed) -------------
__device__ float    g_gate[Nn];
__device__ unsigned g_menc[Gg];
__device__ float    g_s[Gg];
__device__ float    g_num[Gg * FN];
__device__ float    g_cnt[Gg];
__device__ float    g_agg1[Nn * H1c];
__device__ float    g_h1[Nn * H1c];
__device__ float    g_agg2[Nn * H2c];
__device__ float    g_h2sum[Gg * H2c];

// monotonic float<->uint encoding for atomicMax on floats (handles negatives)
__device__ __forceinline__ unsigned enc_f(float f) {
    unsigned b = __float_as_uint(f);
    return (b & 0x80000000u) ? ~b : (b | 0x80000000u);
}
__device__ __forceinline__ float dec_f(unsigned e) {
    unsigned b = (e & 0x80000000u) ? (e ^ 0x80000000u) : ~e;
    return __uint_as_float(b);
}

// ---------------- init: zero scratch ------------------------------------------
__global__ void k_init() {
    int i = blockIdx.x * blockDim.x + threadIdx.x;
    int stride = gridDim.x * blockDim.x;
    for (int t = i; t < Nn * H1c; t += stride) g_agg1[t] = 0.f;
    for (int t = i; t < Nn * H2c; t += stride) g_agg2[t] = 0.f;
    for (int t = i; t < Gg; t += stride) { g_menc[t] = 0u; g_s[t] = 0.f; g_cnt[t] = 0.f; }
    for (int t = i; t < Gg * FN; t += stride) { g_num[t] = 0.f; g_h2sum[t] = 0.f; }
}

// ---------------- gate = relu(x@Wg1+bg1)@wg2+bg2 ; segment max ----------------
__global__ void k_gate(const float* __restrict__ x,
                       const float* __restrict__ wg1, const float* __restrict__ bg1,
                       const float* __restrict__ wg2, const float* __restrict__ bg2,
                       const int* __restrict__ batch) {
    __shared__ float sw1[FN * FN], sb1[FN], sw2[FN], sb2;
    int tid = threadIdx.x;
    if (tid < FN * FN) sw1[tid] = wg1[tid];
    if (tid < FN) { sb1[tid] = bg1[tid]; sw2[tid] = wg2[tid]; }
    if (tid == 0) sb2 = bg2[0];
    __syncthreads();
    int n = blockIdx.x * blockDim.x + tid;
    if (n >= Nn) return;
    float xv[FN];
#pragma unroll
    for (int i = 0; i < FN; i++) xv[i] = x[n * FN + i];
    float g = sb2;
#pragma unroll
    for (int j = 0; j < FN; j++) {
        float h = sb1[j];
#pragma unroll
        for (int i = 0; i < FN; i++) h += xv[i] * sw1[i * FN + j];
        g += fmaxf(h, 0.f) * sw2[j];
    }
    g_gate[n] = g;
    atomicMax(&g_menc[batch[n]], enc_f(g));
}

// ---------------- softmax numerators / denominators / counts ------------------
__global__ void k_att(const float* __restrict__ x, const int* __restrict__ batch) {
    int n = blockIdx.x * blockDim.x + threadIdx.x;
    if (n >= Nn) return;
    int b = batch[n];
    float a = expf(g_gate[n] - dec_f(g_menc[b]));
    atomicAdd(&g_s[b], a);
    atomicAdd(&g_cnt[b], 1.f);
#pragma unroll
    for (int f = 0; f < FN; f++)
        atomicAdd(&g_num[b * FN + f], a * x[n * FN + f]);
}

// ---------------- conv1 edge kernel: fused theta+einsum -----------------------
// msg_o = sum_i x_i * b_e1b[i*32+o] + sum_k h_k * (sum_i x_i * w_e1b[k,i*32+o])
__global__ void k_conv1(const float* __restrict__ x, const float* __restrict__ ea,
                        const float* __restrict__ w_e1a, const float* __restrict__ b_e1a,
                        const float* __restrict__ w_e1b, const float* __restrict__ b_e1b,
                        const int* __restrict__ ei) {
    __shared__ float sw[16 * 512];    // w_e1b [16][16*32]
    __shared__ float sbb[512];        // b_e1b
    __shared__ float swa[FE * 16];    // w_e1a
    __shared__ float sba[16];
    __shared__ float stage[WPB][32];  // [0:16] h, [16:32] x[src]
    int tid = threadIdx.x;
    for (int t = tid; t < 16 * 512; t += blockDim.x) sw[t] = w_e1b[t];
    for (int t = tid; t < 512; t += blockDim.x) sbb[t] = b_e1b[t];
    for (int t = tid; t < FE * 16; t += blockDim.x) swa[t] = w_e1a[t];
    if (tid < 16) sba[tid] = b_e1a[tid];
    __syncthreads();
    int warp = tid >> 5, lane = tid & 31;
    int gw = blockIdx.x * WPB + warp;
    int nw = gridDim.x * WPB;
    for (int e = gw; e < Ee; e += nw) {
        int src = ei[e], tgt = ei[Ee + e];
        if (lane < 16) {
            float acc = sba[lane];
            const float* eap = ea + e * FE;
#pragma unroll
            for (int j = 0; j < FE; j++) acc += eap[j] * swa[j * 16 + lane];
            stage[warp][lane] = fmaxf(acc, 0.f);
            stage[warp][16 + lane] = x[src * FN + lane];
        }
        __syncwarp();
        float xv[FN];
#pragma unroll
        for (int i = 0; i < FN; i++) xv[i] = stage[warp][16 + i];
        float acc = 0.f;
#pragma unroll
        for (int i = 0; i < FN; i++) acc += xv[i] * sbb[i * 32 + lane];
#pragma unroll
        for (int k = 0; k < 16; k++) {
            float hk = stage[warp][k];
            float t = 0.f;
            const float* wr = sw + k * 512 + lane;
#pragma unroll
            for (int i = 0; i < FN; i++) t += xv[i] * wr[i * 32];
            acc += hk * t;
        }
        atomicAdd(&g_agg1[tgt * H1c + lane], acc);
        __syncwarp();
    }
}

// ---------------- node1: h1 = relu(x@w_root1 + b + agg1) ----------------------
__global__ void k_node1(const float* __restrict__ x,
                        const float* __restrict__ wr, const float* __restrict__ br) {
    __shared__ float sw[FN * H1c], sb[H1c];
    int tid = threadIdx.x;
    for (int t = tid; t < FN * H1c; t += blockDim.x) sw[t] = wr[t];
    if (tid < H1c) sb[tid] = br[tid];
    __syncthreads();
    int n = blockIdx.x * blockDim.x + tid;
    if (n >= Nn) return;
    float xv[FN];
#pragma unroll
    for (int i = 0; i < FN; i++) xv[i] = x[n * FN + i];
#pragma unroll
    for (int o = 0; o < H1c; o++) {
        float v = sb[o] + g_agg1[n * H1c + o];
#pragma unroll
        for (int i = 0; i < FN; i++) v += xv[i] * sw[i * H1c + o];
        g_h1[n * H1c + o] = fmaxf(v, 0.f);
    }
}

// ---------------- conv2 edge kernel (in=32, out=16, split i-sum) --------------
// lane: o = lane&15, half = lane>>4, i = 2*ii + half (conflict-free banks)
__global__ void k_conv2(const float* __restrict__ ea,
                        const float* __restrict__ w_e2a, const float* __restrict__ b_e2a,
                        const float* __restrict__ w_e2b, const float* __restrict__ b_e2b,
                        const int* __restrict__ ei) {
    __shared__ float sw[16 * 512];    // w_e2b [16][32*16]
    __shared__ float sbb[512];        // b_e2b
    __shared__ float swa[FE * 16];
    __shared__ float sba[16];
    __shared__ float stage[WPB][48];  // [0:16] h, [16:48] h1[src]
    int tid = threadIdx.x;
    for (int t = tid; t < 16 * 512; t += blockDim.x) sw[t] = w_e2b[t];
    for (int t = tid; t < 512; t += blockDim.x) sbb[t] = b_e2b[t];
    for (int t = tid; t < FE * 16; t += blockDim.x) swa[t] = w_e2a[t];
    if (tid < 16) sba[tid] = b_e2a[tid];
    __syncthreads();
    int warp = tid >> 5, lane = tid & 31;
    int o = lane & 15, half = lane >> 4;
    int gw = blockIdx.x * WPB + warp;
    int nw = gridDim.x * WPB;
    for (int e = gw; e < Ee; e += nw) {
        int src = ei[e], tgt = ei[Ee + e];
        if (lane < 16) {
            float acc = sba[lane];
            const float* eap = ea + e * FE;
#pragma unroll
            for (int j = 0; j < FE; j++) acc += eap[j] * swa[j * 16 + lane];
            stage[warp][lane] = fmaxf(acc, 0.f);
        }
        stage[warp][16 + lane] = g_h1[src * H1c + lane];
        __syncwarp();
        float xv[16];
#pragma unroll
        for (int ii = 0; ii < 16; ii++) xv[ii] = stage[warp][16 + 2 * ii + half];
        float acc = 0.f;
#pragma unroll
        for (int ii = 0; ii < 16; ii++) acc += xv[ii] * sbb[(2 * ii + half) * 16 + o];
#pragma unroll
        for (int k = 0; k < 16; k++) {
            float hk = stage[warp][k];
            float t = 0.f;
            const float* wrp = sw + k * 512 + half * 16 + o;
#pragma unroll
            for (int ii = 0; ii < 16; ii++) t += xv[ii] * wrp[ii * 32];
            acc += hk * t;
        }
        acc += __shfl_xor_sync(0xffffffffu, acc, 16);
        if (lane < 16) atomicAdd(&g_agg2[tgt * H2c + o], acc);
        __syncwarp();
    }
}

// ---------------- node2: h2 = relu(h1@w_root2 + b + agg2); mean-pool sum ------
__global__ void k_node2(const float* __restrict__ wr, const float* __restrict__ br,
                        const int* __restrict__ batch) {
    __shared__ float sw[H1c * H2c], sb[H2c];
    int tid = threadIdx.x;
    for (int t = tid; t < H1c * H2c; t += blockDim.x) sw[t] = wr[t];
    if (tid < H2c) sb[tid] = br[tid];
    __syncthreads();
    int n = blockIdx.x * blockDim.x + tid;
    if (n >= Nn) return;
    float hv[H1c];
#pragma unroll
    for (int i = 0; i < H1c; i++) hv[i] = g_h1[n * H1c + i];
    int b = batch[n];
#pragma unroll
    for (int oo = 0; oo < H2c; oo++) {
        float v = sb[oo] + g_agg2[n * H2c + oo];
#pragma unroll
        for (int i = 0; i < H1c; i++) v += hv[i] * sw[i * H2c + oo];
        atomicAdd(&g_h2sum[b * H2c + oo], fmaxf(v, 0.f));
    }
}

// ---------------- final head per graph ----------------------------------------
__global__ void k_final(float* __restrict__ out,
                        const float* __restrict__ wl1, const float* __restrict__ bl1,
                        const float* __restrict__ wl2, const float* __restrict__ bl2) {
    int g = blockIdx.x * blockDim.x + threadIdx.x;
    if (g >= Gg) return;
    float cnt = fmaxf(g_cnt[g], 1.f);
    float s = g_s[g];
    float invs = (s > 0.f) ? (1.f / s) : 0.f;
    float z[H2c + FN];
#pragma unroll
    for (int o = 0; o < H2c; o++) z[o] = g_h2sum[g * H2c + o] / cnt;
#pragma unroll
    for (int f = 0; f < FN; f++) z[H2c + f] = g_num[g * FN + f] * invs;
    float y[8];
#pragma unroll
    for (int j = 0; j < 8; j++) {
        float v = __ldg(&bl1[j]);
#pragma unroll
        for (int c = 0; c < H2c + FN; c++) v += z[c] * __ldg(&wl1[c * 8 + j]);
        y[j] = v;
    }
    float r = __ldg(&bl2[0]);
#pragma unroll
    for (int j = 0; j < 8; j++) r += y[j] * __ldg(&wl2[j]);
    out[g] = r;
}

// ---------------- launch ------------------------------------------------------
extern "C" void kernel_launch(void* const* d_in, const int* in_sizes, int n_in,
                              void* d_out, int out_size) {
    const float* x       = (const float*)d_in[0];
    const float* ea      = (const float*)d_in[1];
    const float* w_e1a   = (const float*)d_in[2];
    const float* b_e1a   = (const float*)d_in[3];
    const float* w_e1b   = (const float*)d_in[4];
    const float* b_e1b   = (const float*)d_in[5];
    const float* w_root1 = (const float*)d_in[6];
    const float* b_root1 = (const float*)d_in[7];
    const float* w_e2a   = (const float*)d_in[8];
    const float* b_e2a   = (const float*)d_in[9];
    const float* w_e2b   = (const float*)d_in[10];
    const float* b_e2b   = (const float*)d_in[11];
    const float* w_root2 = (const float*)d_in[12];
    const float* b_root2 = (const float*)d_in[13];
    const float* w_g1    = (const float*)d_in[14];
    const float* b_g1    = (const float*)d_in[15];
    const float* w_g2    = (const float*)d_in[16];
    const float* b_g2    = (const float*)d_in[17];
    const float* w_l1    = (const float*)d_in[18];
    const float* b_l1    = (const float*)d_in[19];
    const float* w_l2    = (const float*)d_in[20];
    const float* b_l2    = (const float*)d_in[21];
    const int*   ei      = (const int*)d_in[22];
    const int*   batch   = (const int*)d_in[23];
    float* out = (float*)d_out;

    int nblk = (Nn + 255) / 256;
    k_init<<<512, 256>>>();
    k_gate<<<nblk, 256>>>(x, w_g1, b_g1, w_g2, b_g2, batch);
    k_att<<<nblk, 256>>>(x, batch);
    k_conv1<<<592, 256>>>(x, ea, w_e1a, b_e1a, w_e1b, b_e1b, ei);
    k_node1<<<nblk, 256>>>(x, w_root1, b_root1);
    k_conv2<<<592, 256>>>(ea, w_e2a, b_e2a, w_e2b, b_e2b, ei);
    k_node2<<<nblk, 256>>>(w_root2, b_root2, batch);
    k_final<<<(Gg + 255) / 256, 256>>>(out, w_l1, b_l1, w_l2, b_l2);
}

// round 2
// speedup vs baseline: 1.5018x; 1.5018x over previous
#include <cuda_runtime.h>

// Problem constants
#define Nn 100000
#define Ee 200000
#define Gg 2500
#define FN 16
#define FE 8
#define H1c 32
#define H2c 16

// ---------------- scratch (device globals; no allocation allowed) -------------
__device__ float    g_gate[Nn];
__device__ unsigned g_menc[Gg];
__device__ float    g_s[Gg];
__device__ float    g_num[Gg * FN];
__device__ float    g_cnt[Gg];
__device__ float    g_agg1[Nn * H1c];
__device__ float    g_h1[Nn * H1c];
__device__ float    g_agg2[Nn * H2c];
__device__ float    g_h2sum[Gg * H2c];

// monotonic float<->uint encoding for atomicMax on floats (handles negatives)
__device__ __forceinline__ unsigned enc_f(float f) {
    unsigned b = __float_as_uint(f);
    return (b & 0x80000000u) ? ~b : (b | 0x80000000u);
}
__device__ __forceinline__ float dec_f(unsigned e) {
    unsigned b = (e & 0x80000000u) ? (e ^ 0x80000000u) : ~e;
    return __uint_as_float(b);
}

// ---------------- init: zero scratch ------------------------------------------
__global__ void k_init() {
    int i = blockIdx.x * blockDim.x + threadIdx.x;
    int stride = gridDim.x * blockDim.x;
    for (int t = i; t < Nn * H1c; t += stride) g_agg1[t] = 0.f;
    for (int t = i; t < Nn * H2c; t += stride) g_agg2[t] = 0.f;
    for (int t = i; t < Gg; t += stride) { g_menc[t] = 0u; g_s[t] = 0.f; g_cnt[t] = 0.f; }
    for (int t = i; t < Gg * FN; t += stride) { g_num[t] = 0.f; g_h2sum[t] = 0.f; }
}

// ---------------- gate = relu(x@Wg1+bg1)@wg2+bg2 ; segment max ----------------
__global__ void k_gate(const float* __restrict__ x,
                       const float* __restrict__ wg1, const float* __restrict__ bg1,
                       const float* __restrict__ wg2, const float* __restrict__ bg2,
                       const int* __restrict__ batch) {
    __shared__ float sw1[FN * FN], sb1[FN], sw2[FN], sb2;
    int tid = threadIdx.x;
    if (tid < FN * FN) sw1[tid] = wg1[tid];
    if (tid < FN) { sb1[tid] = bg1[tid]; sw2[tid] = wg2[tid]; }
    if (tid == 0) sb2 = bg2[0];
    __syncthreads();
    int n = blockIdx.x * blockDim.x + tid;
    if (n >= Nn) return;
    float xv[FN];
#pragma unroll
    for (int i = 0; i < FN; i++) xv[i] = x[n * FN + i];
    float g = sb2;
#pragma unroll
    for (int j = 0; j < FN; j++) {
        float h = sb1[j];
#pragma unroll
        for (int i = 0; i < FN; i++) h += xv[i] * sw1[i * FN + j];
        g += fmaxf(h, 0.f) * sw2[j];
    }
    g_gate[n] = g;
    atomicMax(&g_menc[batch[n]], enc_f(g));
}

// ---------------- softmax numerators / denominators / counts ------------------
__global__ void k_att(const float* __restrict__ x, const int* __restrict__ batch) {
    int n = blockIdx.x * blockDim.x + threadIdx.x;
    if (n >= Nn) return;
    int b = batch[n];
    float a = expf(g_gate[n] - dec_f(g_menc[b]));
    atomicAdd(&g_s[b], a);
    atomicAdd(&g_cnt[b], 1.f);
#pragma unroll
    for (int f = 0; f < FN; f++)
        atomicAdd(&g_num[b * FN + f], a * x[n * FN + f]);
}

// ---------------- conv1 edge kernel: one thread per edge, broadcast weights ---
// msg_o = sum_i x_i * bb[i*32+o] + sum_k h_k * (sum_i x_i * wb[k, i*32+o])
__global__ void __launch_bounds__(128) k_conv1(
        const float* __restrict__ x, const float* __restrict__ ea,
        const float* __restrict__ w_e1a, const float* __restrict__ b_e1a,
        const float* __restrict__ w_e1b, const float* __restrict__ b_e1b,
        const int* __restrict__ ei) {
    __shared__ float4 sw4[16 * 16 * 8];   // w_e1b [k][i][o] as float4 over o
    __shared__ float4 sbb4[16 * 8];       // b_e1b [i][o]
    __shared__ float4 swa4[FE * 4];       // w_e1a [j][l] float4 over l
    __shared__ float  sba[16];
    __shared__ float  sh[16][128];        // h[k][tid], conflict-free
    int tid = threadIdx.x;
    for (int t = tid; t < 16 * 16 * 8; t += 128) sw4[t] = ((const float4*)w_e1b)[t];
    for (int t = tid; t < 16 * 8;      t += 128) sbb4[t] = ((const float4*)b_e1b)[t];
    if (tid < FE * 4) swa4[tid] = ((const float4*)w_e1a)[tid];
    if (tid < 16) sba[tid] = b_e1a[tid];
    __syncthreads();

    int e = blockIdx.x * 128 + tid;
    if (e >= Ee) return;
    int src = ei[e], tgt = ei[Ee + e];

    // edge MLP: h = relu(ea @ wa + ba)   [8 -> 16]
    float eav[FE];
    {
        const float4* eap = (const float4*)(ea + e * FE);
        float4 a0 = eap[0], a1 = eap[1];
        eav[0]=a0.x; eav[1]=a0.y; eav[2]=a0.z; eav[3]=a0.w;
        eav[4]=a1.x; eav[5]=a1.y; eav[6]=a1.z; eav[7]=a1.w;
    }
    float hv[16];
#pragma unroll
    for (int l = 0; l < 16; l++) hv[l] = sba[l];
#pragma unroll
    for (int j = 0; j < FE; j++) {
        float c = eav[j];
#pragma unroll
        for (int l4 = 0; l4 < 4; l4++) {
            float4 w = swa4[j * 4 + l4];
            hv[l4*4+0] += c * w.x; hv[l4*4+1] += c * w.y;
            hv[l4*4+2] += c * w.z; hv[l4*4+3] += c * w.w;
        }
    }
#pragma unroll
    for (int l = 0; l < 16; l++) sh[l][tid] = fmaxf(hv[l], 0.f);

    // x[src]
    float xv[FN];
    {
        const float4* xp = (const float4*)(x + src * FN);
#pragma unroll
        for (int q = 0; q < 4; q++) {
            float4 v = xp[q];
            xv[q*4+0]=v.x; xv[q*4+1]=v.y; xv[q*4+2]=v.z; xv[q*4+3]=v.w;
        }
    }

    float acc[32];
#pragma unroll
    for (int o = 0; o < 32; o++) acc[o] = 0.f;

    // bias term: acc[o] += x_i * bb[i][o]
#pragma unroll
    for (int i = 0; i < 16; i++) {
        float c = xv[i];
#pragma unroll
        for (int o4 = 0; o4 < 8; o4++) {
            float4 w = sbb4[i * 8 + o4];
            acc[o4*4+0] += c * w.x; acc[o4*4+1] += c * w.y;
            acc[o4*4+2] += c * w.z; acc[o4*4+3] += c * w.w;
        }
    }
    // main term: rolled k-loop (code size), unrolled i,o
#pragma unroll 1
    for (int k = 0; k < 16; k++) {
        float hk = sh[k][tid];
        const float4* wk = &sw4[k * 128];
#pragma unroll
        for (int i = 0; i < 16; i++) {
            float c = hk * xv[i];
#pragma unroll
            for (int o4 = 0; o4 < 8; o4++) {
                float4 w = wk[i * 8 + o4];
                acc[o4*4+0] += c * w.x; acc[o4*4+1] += c * w.y;
                acc[o4*4+2] += c * w.z; acc[o4*4+3] += c * w.w;
            }
        }
    }
    float* dst = &g_agg1[tgt * H1c];
#pragma unroll
    for (int o = 0; o < 32; o++) atomicAdd(dst + o, acc[o]);
}

// ---------------- node1: h1 = relu(x@w_root1 + b + agg1) ----------------------
__global__ void k_node1(const float* __restrict__ x,
                        const float* __restrict__ wr, const float* __restrict__ br) {
    __shared__ float sw[FN * H1c], sb[H1c];
    int tid = threadIdx.x;
    for (int t = tid; t < FN * H1c; t += blockDim.x) sw[t] = wr[t];
    if (tid < H1c) sb[tid] = br[tid];
    __syncthreads();
    int n = blockIdx.x * blockDim.x + tid;
    if (n >= Nn) return;
    float xv[FN];
#pragma unroll
    for (int i = 0; i < FN; i++) xv[i] = x[n * FN + i];
#pragma unroll
    for (int o = 0; o < H1c; o++) {
        float v = sb[o] + g_agg1[n * H1c + o];
#pragma unroll
        for (int i = 0; i < FN; i++) v += xv[i] * sw[i * H1c + o];
        g_h1[n * H1c + o] = fmaxf(v, 0.f);
    }
}

// ---------------- conv2 edge kernel: one thread per edge ----------------------
// msg_o = sum_i h1_i * (bb[i*16+o] + sum_k h_k * wb[k, i*16+o]), i<32, o<16
__global__ void __launch_bounds__(128) k_conv2(
        const float* __restrict__ ea,
        const float* __restrict__ w_e2a, const float* __restrict__ b_e2a,
        const float* __restrict__ w_e2b, const float* __restrict__ b_e2b,
        const int* __restrict__ ei) {
    __shared__ float4 sw4[16 * 32 * 4];   // w_e2b [k][i][o] float4 over o
    __shared__ float4 sbb4[32 * 4];       // b_e2b [i][o]
    __shared__ float4 swa4[FE * 4];
    __shared__ float  sba[16];
    __shared__ float  sh[16][128];
    int tid = threadIdx.x;
    for (int t = tid; t < 16 * 32 * 4; t += 128) sw4[t] = ((const float4*)w_e2b)[t];
    for (int t = tid; t < 32 * 4;      t += 128) sbb4[t] = ((const float4*)b_e2b)[t];
    if (tid < FE * 4) swa4[tid] = ((const float4*)w_e2a)[tid];
    if (tid < 16) sba[tid] = b_e2a[tid];
    __syncthreads();

    int e = blockIdx.x * 128 + tid;
    if (e >= Ee) return;
    int src = ei[e], tgt = ei[Ee + e];

    float eav[FE];
    {
        const float4* eap = (const float4*)(ea + e * FE);
        float4 a0 = eap[0], a1 = eap[1];
        eav[0]=a0.x; eav[1]=a0.y; eav[2]=a0.z; eav[3]=a0.w;
        eav[4]=a1.x; eav[5]=a1.y; eav[6]=a1.z; eav[7]=a1.w;
    }
    float hv[16];
#pragma unroll
    for (int l = 0; l < 16; l++) hv[l] = sba[l];
#pragma unroll
    for (int j = 0; j < FE; j++) {
        float c = eav[j];
#pragma unroll
        for (int l4 = 0; l4 < 4; l4++) {
            float4 w = swa4[j * 4 + l4];
            hv[l4*4+0] += c * w.x; hv[l4*4+1] += c * w.y;
            hv[l4*4+2] += c * w.z; hv[l4*4+3] += c * w.w;
        }
    }
#pragma unroll
    for (int l = 0; l < 16; l++) sh[l][tid] = fmaxf(hv[l], 0.f);

    // h1[src] : 32 floats
    float xv[H1c];
    {
        const float4* xp = (const float4*)(&g_h1[src * H1c]);
#pragma unroll
        for (int q = 0; q < 8; q++) {
            float4 v = xp[q];
            xv[q*4+0]=v.x; xv[q*4+1]=v.y; xv[q*4+2]=v.z; xv[q*4+3]=v.w;
        }
    }

    float acc[16];
#pragma unroll
    for (int o = 0; o < 16; o++) acc[o] = 0.f;

    // bias term
#pragma unroll
    for (int i = 0; i < 32; i++) {
        float c = xv[i];
#pragma unroll
        for (int o4 = 0; o4 < 4; o4++) {
            float4 w = sbb4[i * 4 + o4];
            acc[o4*4+0] += c * w.x; acc[o4*4+1] += c * w.y;
            acc[o4*4+2] += c * w.z; acc[o4*4+3] += c * w.w;
        }
    }
#pragma unroll 1
    for (int k = 0; k < 16; k++) {
        float hk = sh[k][tid];
        const float4* wk = &sw4[k * 128];
#pragma unroll
        for (int i = 0; i < 32; i++) {
            float c = hk * xv[i];
#pragma unroll
            for (int o4 = 0; o4 < 4; o4++) {
                float4 w = wk[i * 4 + o4];
                acc[o4*4+0] += c * w.x; acc[o4*4+1] += c * w.y;
                acc[o4*4+2] += c * w.z; acc[o4*4+3] += c * w.w;
            }
        }
    }
    float* dst = &g_agg2[tgt * H2c];
#pragma unroll
    for (int o = 0; o < 16; o++) atomicAdd(dst + o, acc[o]);
}

// ---------------- node2: h2 = relu(h1@w_root2 + b + agg2); mean-pool sum ------
__global__ void k_node2(const float* __restrict__ wr, const float* __restrict__ br,
                        const int* __restrict__ batch) {
    __shared__ float sw[H1c * H2c], sb[H2c];
    int tid = threadIdx.x;
    for (int t = tid; t < H1c * H2c; t += blockDim.x) sw[t] = wr[t];
    if (tid < H2c) sb[tid] = br[tid];
    __syncthreads();
    int n = blockIdx.x * blockDim.x + tid;
    if (n >= Nn) return;
    float hv[H1c];
#pragma unroll
    for (int i = 0; i < H1c; i++) hv[i] = g_h1[n * H1c + i];
    int b = batch[n];
#pragma unroll
    for (int oo = 0; oo < H2c; oo++) {
        float v = sb[oo] + g_agg2[n * H2c + oo];
#pragma unroll
        for (int i = 0; i < H1c; i++) v += hv[i] * sw[i * H2c + oo];
        atomicAdd(&g_h2sum[b * H2c + oo], fmaxf(v, 0.f));
    }
}

// ---------------- final head per graph ----------------------------------------
__global__ void k_final(float* __restrict__ out,
                        const float* __restrict__ wl1, const float* __restrict__ bl1,
                        const float* __restrict__ wl2, const float* __restrict__ bl2) {
    int g = blockIdx.x * blockDim.x + threadIdx.x;
    if (g >= Gg) return;
    float cnt = fmaxf(g_cnt[g], 1.f);
    float s = g_s[g];
    float invs = (s > 0.f) ? (1.f / s) : 0.f;
    float z[H2c + FN];
#pragma unroll
    for (int o = 0; o < H2c; o++) z[o] = g_h2sum[g * H2c + o] / cnt;
#pragma unroll
    for (int f = 0; f < FN; f++) z[H2c + f] = g_num[g * FN + f] * invs;
    float y[8];
#pragma unroll
    for (int j = 0; j < 8; j++) {
        float v = __ldg(&bl1[j]);
#pragma unroll
        for (int c = 0; c < H2c + FN; c++) v += z[c] * __ldg(&wl1[c * 8 + j]);
        y[j] = v;
    }
    float r = __ldg(&bl2[0]);
#pragma unroll
    for (int j = 0; j < 8; j++) r += y[j] * __ldg(&wl2[j]);
    out[g] = r;
}

// ---------------- launch ------------------------------------------------------
extern "C" void kernel_launch(void* const* d_in, const int* in_sizes, int n_in,
                              void* d_out, int out_size) {
    const float* x       = (const float*)d_in[0];
    const float* ea      = (const float*)d_in[1];
    const float* w_e1a   = (const float*)d_in[2];
    const float* b_e1a   = (const float*)d_in[3];
    const float* w_e1b   = (const float*)d_in[4];
    const float* b_e1b   = (const float*)d_in[5];
    const float* w_root1 = (const float*)d_in[6];
    const float* b_root1 = (const float*)d_in[7];
    const float* w_e2a   = (const float*)d_in[8];
    const float* b_e2a   = (const float*)d_in[9];
    const float* w_e2b   = (const float*)d_in[10];
    const float* b_e2b   = (const float*)d_in[11];
    const float* w_root2 = (const float*)d_in[12];
    const float* b_root2 = (const float*)d_in[13];
    const float* w_g1    = (const float*)d_in[14];
    const float* b_g1    = (const float*)d_in[15];
    const float* w_g2    = (const float*)d_in[16];
    const float* b_g2    = (const float*)d_in[17];
    const float* w_l1    = (const float*)d_in[18];
    const float* b_l1    = (const float*)d_in[19];
    const float* w_l2    = (const float*)d_in[20];
    const float* b_l2    = (const float*)d_in[21];
    const int*   ei      = (const int*)d_in[22];
    const int*   batch   = (const int*)d_in[23];
    float* out = (float*)d_out;

    int nblk = (Nn + 255) / 256;
    int eblk = (Ee + 127) / 128;
    k_init<<<512, 256>>>();
    k_gate<<<nblk, 256>>>(x, w_g1, b_g1, w_g2, b_g2, batch);
    k_att<<<nblk, 256>>>(x, batch);
    k_conv1<<<eblk, 128>>>(x, ea, w_e1a, b_e1a, w_e1b, b_e1b, ei);
    k_node1<<<nblk, 256>>>(x, w_root1, b_root1);
    k_conv2<<<eblk, 128>>>(ea, w_e2a, b_e2a, w_e2b, b_e2b, ei);
    k_node2<<<nblk, 256>>>(w_root2, b_root2, batch);
    k_final<<<(Gg + 255) / 256, 256>>>(out, w_l1, b_l1, w_l2, b_l2);
}

// round 3
// speedup vs baseline: 1.5270x; 1.0168x over previous
#include <cuda_runtime.h>

// Problem constants
#define Nn 100000
#define Ee 200000
#define Gg 2500
#define FN 16
#define FE 8
#define H1c 32
#define H2c 16

// ---------------- scratch (device globals; no allocation allowed) -------------
__device__ float    g_gate[Nn];
__device__ unsigned g_menc[Gg];
__device__ float    g_s[Gg];
__device__ float    g_num[Gg * FN];
__device__ float    g_cnt[Gg];
__device__ float    g_agg1[Nn * H1c];
__device__ float    g_h1[Nn * H1c];
__device__ float    g_agg2[Nn * H2c];
__device__ float    g_h2sum[Gg * H2c];

// monotonic float<->uint encoding for atomicMax on floats
__device__ __forceinline__ unsigned enc_f(float f) {
    unsigned b = __float_as_uint(f);
    return (b & 0x80000000u) ? ~b : (b | 0x80000000u);
}
__device__ __forceinline__ float dec_f(unsigned e) {
    unsigned b = (e & 0x80000000u) ? (e ^ 0x80000000u) : ~e;
    return __uint_as_float(b);
}

// ---------------- init: zero scratch ------------------------------------------
__global__ void k_init() {
    int i = blockIdx.x * blockDim.x + threadIdx.x;
    int stride = gridDim.x * blockDim.x;
    for (int t = i; t < Nn * H1c; t += stride) g_agg1[t] = 0.f;
    for (int t = i; t < Nn * H2c; t += stride) g_agg2[t] = 0.f;
    for (int t = i; t < Gg; t += stride) { g_menc[t] = 0u; g_s[t] = 0.f; g_cnt[t] = 0.f; }
    for (int t = i; t < Gg * FN; t += stride) { g_num[t] = 0.f; g_h2sum[t] = 0.f; }
}

// ---------------- gate = relu(x@Wg1+bg1)@wg2+bg2 ; segment max ----------------
__global__ void k_gate(const float* __restrict__ x,
                       const float* __restrict__ wg1, const float* __restrict__ bg1,
                       const float* __restrict__ wg2, const float* __restrict__ bg2,
                       const int* __restrict__ batch) {
    __shared__ float sw1[FN * FN], sb1[FN], sw2[FN], sb2;
    int tid = threadIdx.x;
    if (tid < FN * FN) sw1[tid] = wg1[tid];
    if (tid < FN) { sb1[tid] = bg1[tid]; sw2[tid] = wg2[tid]; }
    if (tid == 0) sb2 = bg2[0];
    __syncthreads();
    int n = blockIdx.x * blockDim.x + tid;
    if (n >= Nn) return;
    float xv[FN];
#pragma unroll
    for (int i = 0; i < FN; i++) xv[i] = x[n * FN + i];
    float g = sb2;
#pragma unroll
    for (int j = 0; j < FN; j++) {
        float h = sb1[j];
#pragma unroll
        for (int i = 0; i < FN; i++) h += xv[i] * sw1[i * FN + j];
        g += fmaxf(h, 0.f) * sw2[j];
    }
    g_gate[n] = g;
    atomicMax(&g_menc[batch[n]], enc_f(g));
}

// ---------------- softmax numerators / denominators / counts ------------------
__global__ void k_att(const float* __restrict__ x, const int* __restrict__ batch) {
    int n = blockIdx.x * blockDim.x + threadIdx.x;
    if (n >= Nn) return;
    int b = batch[n];
    float a = expf(g_gate[n] - dec_f(g_menc[b]));
    atomicAdd(&g_s[b], a);
    atomicAdd(&g_cnt[b], 1.f);
#pragma unroll
    for (int f = 0; f < FN; f++)
        atomicAdd(&g_num[b * FN + f], a * x[n * FN + f]);
}

// ---------------- conv1: edge-pair per thread, o-half split -------------------
// thread t: pair slots (t&~1, t|1) -> edges e0,e1; output half = t&1 (16 outs)
__global__ void __launch_bounds__(128) k_conv1(
        const float* __restrict__ x, const float* __restrict__ ea,
        const float* __restrict__ w_e1a, const float* __restrict__ b_e1a,
        const float* __restrict__ w_e1b, const float* __restrict__ b_e1b,
        const int* __restrict__ ei) {
    __shared__ float4 sw4[16 * 16 * 8];   // w_e1b [k][i][o/4]
    __shared__ float4 sbb4[16 * 8];       // b_e1b [i][o/4]
    __shared__ float4 swa4[FE * 4];
    __shared__ float  sba[16];
    __shared__ float  sh[16][128];        // h[k][edge-slot]
    int tid = threadIdx.x;
    for (int t = tid; t < 16 * 16 * 8; t += 128) sw4[t] = ((const float4*)w_e1b)[t];
    for (int t = tid; t < 16 * 8;      t += 128) sbb4[t] = ((const float4*)b_e1b)[t];
    if (tid < FE * 4) swa4[tid] = ((const float4*)w_e1a)[tid];
    if (tid < 16) sba[tid] = b_e1a[tid];
    __syncthreads();

    int eBase = blockIdx.x * 128;
    int myE = eBase + tid;
    // edge MLP for my staged edge
    if (myE < Ee) {
        const float4* eap = (const float4*)(ea + myE * FE);
        float4 a0 = eap[0], a1 = eap[1];
        float eav[FE] = {a0.x,a0.y,a0.z,a0.w,a1.x,a1.y,a1.z,a1.w};
        float hv[16];
#pragma unroll
        for (int l = 0; l < 16; l++) hv[l] = sba[l];
#pragma unroll
        for (int j = 0; j < FE; j++) {
            float c = eav[j];
#pragma unroll
            for (int l4 = 0; l4 < 4; l4++) {
                float4 w = swa4[j * 4 + l4];
                hv[l4*4+0] += c * w.x; hv[l4*4+1] += c * w.y;
                hv[l4*4+2] += c * w.z; hv[l4*4+3] += c * w.w;
            }
        }
#pragma unroll
        for (int l = 0; l < 16; l++) sh[l][tid] = fmaxf(hv[l], 0.f);
    } else {
#pragma unroll
        for (int l = 0; l < 16; l++) sh[l][tid] = 0.f;
    }
    __syncwarp();

    int ohalf = tid & 1;
    int slot0 = tid & ~1;
    int e0 = eBase + slot0, e1 = e0 + 1;
    bool v0 = e0 < Ee, v1 = e1 < Ee;
    int src0 = v0 ? ei[e0] : 0, tgt0 = v0 ? ei[Ee + e0] : 0;
    int src1 = v1 ? ei[e1] : 0, tgt1 = v1 ? ei[Ee + e1] : 0;

    float xv0[FN], xv1[FN];
    {
        const float4* p0 = (const float4*)(x + src0 * FN);
        const float4* p1 = (const float4*)(x + src1 * FN);
#pragma unroll
        for (int q = 0; q < 4; q++) {
            float4 a = p0[q], b = p1[q];
            xv0[q*4+0]=a.x; xv0[q*4+1]=a.y; xv0[q*4+2]=a.z; xv0[q*4+3]=a.w;
            xv1[q*4+0]=b.x; xv1[q*4+1]=b.y; xv1[q*4+2]=b.z; xv1[q*4+3]=b.w;
        }
    }

    float acc0[16], acc1[16];
#pragma unroll
    for (int o = 0; o < 16; o++) { acc0[o] = 0.f; acc1[o] = 0.f; }

    // bias term
#pragma unroll
    for (int i = 0; i < 16; i++) {
        float c0 = xv0[i], c1 = xv1[i];
#pragma unroll
        for (int o4 = 0; o4 < 4; o4++) {
            float4 w = sbb4[i * 8 + ohalf * 4 + o4];
            acc0[o4*4+0] += c0*w.x; acc0[o4*4+1] += c0*w.y;
            acc0[o4*4+2] += c0*w.z; acc0[o4*4+3] += c0*w.w;
            acc1[o4*4+0] += c1*w.x; acc1[o4*4+1] += c1*w.y;
            acc1[o4*4+2] += c1*w.z; acc1[o4*4+3] += c1*w.w;
        }
    }
    // main term
#pragma unroll 1
    for (int k = 0; k < 16; k++) {
        float hk0 = sh[k][slot0], hk1 = sh[k][slot0 + 1];
        const float4* wk = &sw4[k * 128 + ohalf * 4];
#pragma unroll
        for (int i = 0; i < 16; i++) {
            float c0 = hk0 * xv0[i], c1 = hk1 * xv1[i];
#pragma unroll
            for (int o4 = 0; o4 < 4; o4++) {
                float4 w = wk[i * 8 + o4];
                acc0[o4*4+0] += c0*w.x; acc0[o4*4+1] += c0*w.y;
                acc0[o4*4+2] += c0*w.z; acc0[o4*4+3] += c0*w.w;
                acc1[o4*4+0] += c1*w.x; acc1[o4*4+1] += c1*w.y;
                acc1[o4*4+2] += c1*w.z; acc1[o4*4+3] += c1*w.w;
            }
        }
    }
    if (v0) {
        float* dst = &g_agg1[tgt0 * H1c + ohalf * 16];
#pragma unroll
        for (int o = 0; o < 16; o++) atomicAdd(dst + o, acc0[o]);
    }
    if (v1) {
        float* dst = &g_agg1[tgt1 * H1c + ohalf * 16];
#pragma unroll
        for (int o = 0; o < 16; o++) atomicAdd(dst + o, acc1[o]);
    }
}

// ---------------- node1: h1 = relu(x@w_root1 + b + agg1) ----------------------
__global__ void k_node1(const float* __restrict__ x,
                        const float* __restrict__ wr, const float* __restrict__ br) {
    __shared__ float sw[FN * H1c], sb[H1c];
    int tid = threadIdx.x;
    for (int t = tid; t < FN * H1c; t += blockDim.x) sw[t] = wr[t];
    if (tid < H1c) sb[tid] = br[tid];
    __syncthreads();
    int n = blockIdx.x * blockDim.x + tid;
    if (n >= Nn) return;
    float xv[FN];
#pragma unroll
    for (int i = 0; i < FN; i++) xv[i] = x[n * FN + i];
#pragma unroll
    for (int o = 0; o < H1c; o++) {
        float v = sb[o] + g_agg1[n * H1c + o];
#pragma unroll
        for (int i = 0; i < FN; i++) v += xv[i] * sw[i * H1c + o];
        g_h1[n * H1c + o] = fmaxf(v, 0.f);
    }
}

// ---------------- conv2: edge-pair per thread, i-half split -------------------
// thread t: edges (e0,e1), input half = t&1 (16 of 32 inputs), full 16 outs;
// pair-reduce via shfl_xor(.,1) then even lane writes e0, odd writes e1.
__global__ void __launch_bounds__(128) k_conv2(
        const float* __restrict__ ea,
        const float* __restrict__ w_e2a, const float* __restrict__ b_e2a,
        const float* __restrict__ w_e2b, const float* __restrict__ b_e2b,
        const int* __restrict__ ei) {
    __shared__ float4 sw4[16 * 32 * 4];   // w_e2b [k][i][o/4]
    __shared__ float4 sbb4[32 * 4];
    __shared__ float4 swa4[FE * 4];
    __shared__ float  sba[16];
    __shared__ float  sh[16][128];
    int tid = threadIdx.x;
    for (int t = tid; t < 16 * 32 * 4; t += 128) sw4[t] = ((const float4*)w_e2b)[t];
    for (int t = tid; t < 32 * 4;      t += 128) sbb4[t] = ((const float4*)b_e2b)[t];
    if (tid < FE * 4) swa4[tid] = ((const float4*)w_e2a)[tid];
    if (tid < 16) sba[tid] = b_e2a[tid];
    __syncthreads();

    int eBase = blockIdx.x * 128;
    int myE = eBase + tid;
    if (myE < Ee) {
        const float4* eap = (const float4*)(ea + myE * FE);
        float4 a0 = eap[0], a1 = eap[1];
        float eav[FE] = {a0.x,a0.y,a0.z,a0.w,a1.x,a1.y,a1.z,a1.w};
        float hv[16];
#pragma unroll
        for (int l = 0; l < 16; l++) hv[l] = sba[l];
#pragma unroll
        for (int j = 0; j < FE; j++) {
            float c = eav[j];
#pragma unroll
            for (int l4 = 0; l4 < 4; l4++) {
                float4 w = swa4[j * 4 + l4];
                hv[l4*4+0] += c * w.x; hv[l4*4+1] += c * w.y;
                hv[l4*4+2] += c * w.z; hv[l4*4+3] += c * w.w;
            }
        }
#pragma unroll
        for (int l = 0; l < 16; l++) sh[l][tid] = fmaxf(hv[l], 0.f);
    } else {
#pragma unroll
        for (int l = 0; l < 16; l++) sh[l][tid] = 0.f;
    }
    __syncwarp();

    int ihalf = tid & 1;
    int slot0 = tid & ~1;
    int e0 = eBase + slot0, e1 = e0 + 1;
    bool v0 = e0 < Ee, v1 = e1 < Ee;
    int src0 = v0 ? ei[e0] : 0, tgt0 = v0 ? ei[Ee + e0] : 0;
    int src1 = v1 ? ei[e1] : 0, tgt1 = v1 ? ei[Ee + e1] : 0;

    float xv0[16], xv1[16];
    {
        const float4* p0 = (const float4*)(&g_h1[src0 * H1c + ihalf * 16]);
        const float4* p1 = (const float4*)(&g_h1[src1 * H1c + ihalf * 16]);
#pragma unroll
        for (int q = 0; q < 4; q++) {
            float4 a = p0[q], b = p1[q];
            xv0[q*4+0]=a.x; xv0[q*4+1]=a.y; xv0[q*4+2]=a.z; xv0[q*4+3]=a.w;
            xv1[q*4+0]=b.x; xv1[q*4+1]=b.y; xv1[q*4+2]=b.z; xv1[q*4+3]=b.w;
        }
    }

    float acc0[16], acc1[16];
#pragma unroll
    for (int o = 0; o < 16; o++) { acc0[o] = 0.f; acc1[o] = 0.f; }

    // bias term (over this thread's i-half)
#pragma unroll
    for (int ii = 0; ii < 16; ii++) {
        float c0 = xv0[ii], c1 = xv1[ii];
#pragma unroll
        for (int o4 = 0; o4 < 4; o4++) {
            float4 w = sbb4[(ihalf * 16 + ii) * 4 + o4];
            acc0[o4*4+0] += c0*w.x; acc0[o4*4+1] += c0*w.y;
            acc0[o4*4+2] += c0*w.z; acc0[o4*4+3] += c0*w.w;
            acc1[o4*4+0] += c1*w.x; acc1[o4*4+1] += c1*w.y;
            acc1[o4*4+2] += c1*w.z; acc1[o4*4+3] += c1*w.w;
        }
    }
#pragma unroll 1
    for (int k = 0; k < 16; k++) {
        float hk0 = sh[k][slot0], hk1 = sh[k][slot0 + 1];
        const float4* wk = &sw4[k * 128 + ihalf * 64];
#pragma unroll
        for (int ii = 0; ii < 16; ii++) {
            float c0 = hk0 * xv0[ii], c1 = hk1 * xv1[ii];
#pragma unroll
            for (int o4 = 0; o4 < 4; o4++) {
                float4 w = wk[ii * 4 + o4];
                acc0[o4*4+0] += c0*w.x; acc0[o4*4+1] += c0*w.y;
                acc0[o4*4+2] += c0*w.z; acc0[o4*4+3] += c0*w.w;
                acc1[o4*4+0] += c1*w.x; acc1[o4*4+1] += c1*w.y;
                acc1[o4*4+2] += c1*w.z; acc1[o4*4+3] += c1*w.w;
            }
        }
    }
    // pair reduction across i-halves
#pragma unroll
    for (int o = 0; o < 16; o++) {
        acc0[o] += __shfl_xor_sync(0xffffffffu, acc0[o], 1);
        acc1[o] += __shfl_xor_sync(0xffffffffu, acc1[o], 1);
    }
    if (ihalf == 0) {
        if (v0) {
            float* dst = &g_agg2[tgt0 * H2c];
#pragma unroll
            for (int o = 0; o < 16; o++) atomicAdd(dst + o, acc0[o]);
        }
    } else {
        if (v1) {
            float* dst = &g_agg2[tgt1 * H2c];
#pragma unroll
            for (int o = 0; o < 16; o++) atomicAdd(dst + o, acc1[o]);
        }
    }
}

// ---------------- node2: h2 = relu(h1@w_root2 + b + agg2); mean-pool sum ------
__global__ void k_node2(const float* __restrict__ wr, const float* __restrict__ br,
                        const int* __restrict__ batch) {
    __shared__ float sw[H1c * H2c], sb[H2c];
    int tid = threadIdx.x;
    for (int t = tid; t < H1c * H2c; t += blockDim.x) sw[t] = wr[t];
    if (tid < H2c) sb[tid] = br[tid];
    __syncthreads();
    int n = blockIdx.x * blockDim.x + tid;
    if (n >= Nn) return;
    float hv[H1c];
#pragma unroll
    for (int i = 0; i < H1c; i++) hv[i] = g_h1[n * H1c + i];
    int b = batch[n];
#pragma unroll
    for (int oo = 0; oo < H2c; oo++) {
        float v = sb[oo] + g_agg2[n * H2c + oo];
#pragma unroll
        for (int i = 0; i < H1c; i++) v += hv[i] * sw[i * H2c + oo];
        atomicAdd(&g_h2sum[b * H2c + oo], fmaxf(v, 0.f));
    }
}

// ---------------- final head per graph ----------------------------------------
__global__ void k_final(float* __restrict__ out,
                        const float* __restrict__ wl1, const float* __restrict__ bl1,
                        const float* __restrict__ wl2, const float* __restrict__ bl2) {
    int g = blockIdx.x * blockDim.x + threadIdx.x;
    if (g >= Gg) return;
    float cnt = fmaxf(g_cnt[g], 1.f);
    float s = g_s[g];
    float invs = (s > 0.f) ? (1.f / s) : 0.f;
    float z[H2c + FN];
#pragma unroll
    for (int o = 0; o < H2c; o++) z[o] = g_h2sum[g * H2c + o] / cnt;
#pragma unroll
    for (int f = 0; f < FN; f++) z[H2c + f] = g_num[g * FN + f] * invs;
    float y[8];
#pragma unroll
    for (int j = 0; j < 8; j++) {
        float v = __ldg(&bl1[j]);
#pragma unroll
        for (int c = 0; c < H2c + FN; c++) v += z[c] * __ldg(&wl1[c * 8 + j]);
        y[j] = v;
    }
    float r = __ldg(&bl2[0]);
#pragma unroll
    for (int j = 0; j < 8; j++) r += y[j] * __ldg(&wl2[j]);
    out[g] = r;
}

// ---------------- launch ------------------------------------------------------
extern "C" void kernel_launch(void* const* d_in, const int* in_sizes, int n_in,
                              void* d_out, int out_size) {
    const float* x       = (const float*)d_in[0];
    const float* ea      = (const float*)d_in[1];
    const float* w_e1a   = (const float*)d_in[2];
    const float* b_e1a   = (const float*)d_in[3];
    const float* w_e1b   = (const float*)d_in[4];
    const float* b_e1b   = (const float*)d_in[5];
    const float* w_root1 = (const float*)d_in[6];
    const float* b_root1 = (const float*)d_in[7];
    const float* w_e2a   = (const float*)d_in[8];
    const float* b_e2a   = (const float*)d_in[9];
    const float* w_e2b   = (const float*)d_in[10];
    const float* b_e2b   = (const float*)d_in[11];
    const float* w_root2 = (const float*)d_in[12];
    const float* b_root2 = (const float*)d_in[13];
    const float* w_g1    = (const float*)d_in[14];
    const float* b_g1    = (const float*)d_in[15];
    const float* w_g2    = (const float*)d_in[16];
    const float* b_g2    = (const float*)d_in[17];
    const float* w_l1    = (const float*)d_in[18];
    const float* b_l1    = (const float*)d_in[19];
    const float* w_l2    = (const float*)d_in[20];
    const float* b_l2    = (const float*)d_in[21];
    const int*   ei      = (const int*)d_in[22];
    const int*   batch   = (const int*)d_in[23];
    float* out = (float*)d_out;

    int nblk = (Nn + 255) / 256;
    int eblk = (Ee + 127) / 128;
    k_init<<<512, 256>>>();
    k_gate<<<nblk, 256>>>(x, w_g1, b_g1, w_g2, b_g2, batch);
    k_att<<<nblk, 256>>>(x, batch);
    k_conv1<<<eblk, 128>>>(x, ea, w_e1a, b_e1a, w_e1b, b_e1b, ei);
    k_node1<<<nblk, 256>>>(x, w_root1, b_root1);
    k_conv2<<<eblk, 128>>>(ea, w_e2a, b_e2a, w_e2b, b_e2b, ei);
    k_node2<<<nblk, 256>>>(w_root2, b_root2, batch);
    k_final<<<(Gg + 255) / 256, 256>>>(out, w_l1, b_l1, w_l2, b_l2);
}